// round 16
// baseline (speedup 1.0000x reference)
#include <cuda_runtime.h>
#include <cuda_bf16.h>
#include <math_constants.h>
#include <cstdint>

// VectorQuantizer (per-dimension scalar codebooks), SINGLE kernel.
// Each block (256 thr) owns 4 dims x 512-batch chunk:
//   1) register-resident bitonic sort of its 4 codebook dims
//      (2 warps/dim, 8 elems/lane; shfl for j<=16, in-reg for j=32..128,
//       one smem exchange for j=256) -> sorted codes in smem
//   2) Voronoi midpoints -> padded smem
//   3) 8 interleaved lower_bound searches per thread (2 b x 4 dims)
//   4) deterministic MSE loss via last-block finalize
//   z: [B, D] f32 (B=2048, D=128); codebooks: [D, K] f32 (K=512)

#define VQ_D 128
#define VQ_K 512
#define VQ_THREADS 256
#define NDIMS 4
#define VQ_BPT 2
#define CHUNK_B (VQ_THREADS * VQ_BPT)        // 512
#define PADIDX(i) ((i) + ((i) >> 5))
#define PADK (VQ_K + (VQ_K >> 5))            // 528

__device__ float        g_partials[1024];
__device__ unsigned int g_count = 0;

// compare-exchange across lanes (j<=16): element x at global index i
__device__ __forceinline__ float cmpx(float x, int i, int j, int k)
{
    float y = __shfl_xor_sync(0xffffffffu, x, j);
    bool keepmin = (((i & j) == 0) == ((i & k) == 0));
    return keepmin ? fminf(x, y) : fmaxf(x, y);
}

// one bitonic merge step for size K; layout: i = h*256 + r*32 + lane
template<int K>
__device__ __forceinline__ void merge_k(float (&v)[8], int lane, int h, int di,
                                        float (*ss)[VQ_K])
{
#pragma unroll
    for (int j = K / 2; j >= 1; j >>= 1) {
        if (j == 256) {
            // cross-warp exchange via smem (k=512 => ascending: h0 keeps min)
            __syncthreads();
#pragma unroll
            for (int r = 0; r < 8; r++)
                ss[di][h * 256 + r * 32 + lane] = v[r];
            __syncthreads();
#pragma unroll
            for (int r = 0; r < 8; r++) {
                float o = ss[di][(h ^ 1) * 256 + r * 32 + lane];
                v[r] = h ? fmaxf(v[r], o) : fminf(v[r], o);
            }
        } else if (j >= 32) {
            const int rj = j >> 5;              // 1, 2, 4
#pragma unroll
            for (int r = 0; r < 8; r++) {
                if ((r & rj) == 0) {
                    int rh = r | rj;
                    int i0 = h * 256 + r * 32;  // lane-independent bits
                    bool up = ((i0 & K) == 0);
                    float a = v[r], bb = v[rh];
                    if ((a > bb) == up) { v[r] = bb; v[rh] = a; }
                }
            }
        } else {
#pragma unroll
            for (int r = 0; r < 8; r++)
                v[r] = cmpx(v[r], h * 256 + r * 32 + lane, j, K);
        }
    }
}

__global__ void __launch_bounds__(VQ_THREADS)
vq_kernel(const float4* __restrict__ z4,
          const float* __restrict__ cb,
          float* __restrict__ qout,      // may be null
          float* __restrict__ loss_out,  // may be null
          int nb, float inv_n, int vec_ok)
{
    __shared__ float ss  [NDIMS][VQ_K];    // sorted codes
    __shared__ float smid[NDIMS][PADK];    // padded midpoints
    __shared__ float swred[VQ_THREADS / 32];
    __shared__ float sblock;
    __shared__ int   s_is_last;

    const int dg   = blockIdx.x;           // dim group 0..31
    const int d0   = dg * NDIMS;
    const int tid  = threadIdx.x;
    const int lane = tid & 31;
    const int wid  = tid >> 5;
    const int di   = wid >> 1;             // this warp's dim (0..3)
    const int h    = wid & 1;              // half (0..1)

    // ---- prefetch z for two batch elements (hides under sort) ----
    const int b0 = blockIdx.y * CHUNK_B + tid;
    const int b1 = b0 + VQ_THREADS;
    const bool v0 = (b0 < nb), v1 = (b1 < nb);
    float4 zv0 = v0 ? z4[b0 * (VQ_D / 4) + dg] : make_float4(0.f, 0.f, 0.f, 0.f);
    float4 zv1 = v1 ? z4[b1 * (VQ_D / 4) + dg] : make_float4(0.f, 0.f, 0.f, 0.f);

    // ---- load this warp's 256 codebook elements (8 regs, coalesced) ----
    float v[8];
#pragma unroll
    for (int r = 0; r < 8; r++)
        v[r] = cb[(d0 + di) * VQ_K + h * 256 + r * 32 + lane];

    // ---- register bitonic sort of 512 per dim ----
    merge_k<2>(v, lane, h, di, ss);
    merge_k<4>(v, lane, h, di, ss);
    merge_k<8>(v, lane, h, di, ss);
    merge_k<16>(v, lane, h, di, ss);
    merge_k<32>(v, lane, h, di, ss);
    merge_k<64>(v, lane, h, di, ss);
    merge_k<128>(v, lane, h, di, ss);
    merge_k<256>(v, lane, h, di, ss);
    merge_k<512>(v, lane, h, di, ss);

    // publish sorted codes (sync: partner may still be reading ss from j=256)
    __syncthreads();
#pragma unroll
    for (int r = 0; r < 8; r++)
        ss[di][h * 256 + r * 32 + lane] = v[r];
    __syncthreads();

    // ---- Voronoi midpoints (padded) ----
#pragma unroll
    for (int i = tid; i < NDIMS * VQ_K; i += VQ_THREADS) {
        int dd = i >> 9;
        int e  = i & (VQ_K - 1);
        smid[dd][PADIDX(e)] =
            (e < VQ_K - 1) ? 0.5f * (ss[dd][e] + ss[dd][e + 1]) : CUDART_INF_F;
    }
    __syncthreads();

    // ---- 8 interleaved lower_bound searches (2 b x 4 dims) ----
    const float zr[8] = { zv0.x, zv0.y, zv0.z, zv0.w,
                          zv1.x, zv1.y, zv1.z, zv1.w };
    int p[8];
#pragma unroll
    for (int c = 0; c < 8; c++) p[c] = 0;
#pragma unroll
    for (int step = VQ_K / 2; step >= 1; step >>= 1) {
#pragma unroll
        for (int c = 0; c < 8; c++)
            if (smid[c & 3][PADIDX(p[c] + step - 1)] < zr[c]) p[c] += step;
    }
    float q[8];
#pragma unroll
    for (int c = 0; c < 8; c++)
        q[c] = ss[c & 3][p[c]];            // code gather from smem

    float acc = 0.0f;
    if (v0) {
        float e0 = q[0] - zr[0], e1 = q[1] - zr[1];
        float e2 = q[2] - zr[2], e3 = q[3] - zr[3];
        acc += e0 * e0 + e1 * e1 + e2 * e2 + e3 * e3;
        if (qout) {
            float o0 = zr[0] + (q[0] - zr[0]);
            float o1 = zr[1] + (q[1] - zr[1]);
            float o2 = zr[2] + (q[2] - zr[2]);
            float o3 = zr[3] + (q[3] - zr[3]);
            if (vec_ok) {
                reinterpret_cast<float4*>(qout)[b0 * (VQ_D / 4) + dg] =
                    make_float4(o0, o1, o2, o3);
            } else {
                float* qp = qout + b0 * VQ_D + d0;
                qp[0] = o0; qp[1] = o1; qp[2] = o2; qp[3] = o3;
            }
        }
    }
    if (v1) {
        float e4 = q[4] - zr[4], e5 = q[5] - zr[5];
        float e6 = q[6] - zr[6], e7 = q[7] - zr[7];
        acc += e4 * e4 + e5 * e5 + e6 * e6 + e7 * e7;
        if (qout) {
            float o4 = zr[4] + (q[4] - zr[4]);
            float o5 = zr[5] + (q[5] - zr[5]);
            float o6 = zr[6] + (q[6] - zr[6]);
            float o7 = zr[7] + (q[7] - zr[7]);
            if (vec_ok) {
                reinterpret_cast<float4*>(qout)[b1 * (VQ_D / 4) + dg] =
                    make_float4(o4, o5, o6, o7);
            } else {
                float* qp = qout + b1 * VQ_D + d0;
                qp[0] = o4; qp[1] = o5; qp[2] = o6; qp[3] = o7;
            }
        }
    }

    // ---- block loss reduction (deterministic) ----
#pragma unroll
    for (int o = 16; o > 0; o >>= 1)
        acc += __shfl_down_sync(0xffffffffu, acc, o);
    if (lane == 0) swred[wid] = acc;
    __syncthreads();
    if (tid == 0) {
        float t = 0.0f;
#pragma unroll
        for (int ww = 0; ww < VQ_THREADS / 32; ww++) t += swred[ww];
        sblock = t;
    }
    __syncthreads();

    // ---- cross-block finalize (last block, deterministic order) ----
    const int nblocks = gridDim.x * gridDim.y;
    const int bindex  = blockIdx.y * gridDim.x + blockIdx.x;
    if (tid == 0) {
        g_partials[bindex] = sblock;
        __threadfence();
        unsigned int c = atomicAdd(&g_count, 1u);
        s_is_last = (c == (unsigned int)(nblocks - 1));
    }
    __syncthreads();

    if (s_is_last && tid < 32) {
        __threadfence();
        float t = 0.0f;
        for (int i = lane; i < nblocks; i += 32)
            t += g_partials[i];
#pragma unroll
        for (int o = 16; o > 0; o >>= 1)
            t += __shfl_down_sync(0xffffffffu, t, o);
        if (lane == 0) {
            if (loss_out) *loss_out = t * inv_n;
            g_count = 0;   // reset for next graph replay
        }
    }
}

extern "C" void kernel_launch(void* const* d_in, const int* in_sizes, int n_in,
                              void* d_out, int out_size)
{
    const float* z  = (const float*)d_in[0];   // [B, D]
    const float* cb = (const float*)d_in[1];   // [D, K]
    float* out = (float*)d_out;

    const int nb       = in_sizes[0] / VQ_D;   // B
    const int bd_total = nb * VQ_D;

    float* loss_ptr = nullptr;
    float* q_ptr    = nullptr;
    if (out_size == bd_total + 1)      { loss_ptr = out; q_ptr = out + 1; }
    else if (out_size == bd_total)     { q_ptr = out; }
    else if (out_size == 1)            { loss_ptr = out; }
    else                               { q_ptr = out; }

    int chunks = (nb + CHUNK_B - 1) / CHUNK_B;     // 4 for B=2048
    if (chunks > 32) chunks = 32;                  // g_partials bound

    float inv_n = 1.0f / (float)bd_total;
    int vec_ok = (q_ptr != nullptr) && ((((std::uintptr_t)q_ptr) & 15) == 0);

    dim3 grid(VQ_D / NDIMS, chunks);               // (32, 4) = 128 blocks: 1 wave
    vq_kernel<<<grid, VQ_THREADS>>>(
        (const float4*)z, cb, q_ptr, loss_ptr, nb, inv_n, vec_ok);
}